// round 1
// baseline (speedup 1.0000x reference)
#include <cuda_runtime.h>
#include <cuda_bf16.h>
#include <stdint.h>

#define NB 4
#define NC 256
#define NHW 4096
#define NL 512

// ---------------- scratch (no allocations allowed) ----------------
__device__ float    g_Ql  [NB*NHW];
__device__ float    g_Qdis[NB*NHW];
__device__ float    g_Sdis[NB*NHW];
__device__ float    g_winv[NB*NHW];          // Sl/|S_col| (0 if Sl==0 or zero col)
__device__ float    g_qinv[NB*NHW];          // 1/|Q_col| (0 if zero col)
__device__ int      g_sim [NB*NHW];          // float bits, non-negative; init 0 each launch
__device__ uint32_t g_A   [NB*NHW*(NC/2)];   // bf16x2: [b][s][kp] kp packs (2kp,2kp+1)  (8MB)
__device__ uint32_t g_Bm  [NB*(NC/2)*NHW];   // bf16x2: [b][kp][q]                        (8MB)

static __device__ __forceinline__ uint32_t packbf2(float lo, float hi) {
    __nv_bfloat162 t = __floats2bfloat162_rn(lo, hi);   // x = lo (low 16 bits), y = hi
    return *reinterpret_cast<uint32_t*>(&t);
}

// ---------------- K1: labels, disrupt masks, column norms, sim init ----------------
__global__ void k_prep(const float* __restrict__ Qf, const float* __restrict__ Sf,
                       const float* __restrict__ Qlab, const float* __restrict__ Slab,
                       const float* __restrict__ qbg, const float* __restrict__ sbg)
{
    int idx = blockIdx.x * blockDim.x + threadIdx.x;    // NB*NHW threads
    int b = idx >> 12;
    int q = idx & (NHW - 1);
    int h = q >> 6, w = q & 63;
    int lab = (h * 8) * NL + (w * 8);                   // nearest resize 512->64
    float ql = Qlab[b * NL * NL + lab];
    float sl = Slab[b * NL * NL + lab];
    // jnp.argmax over 2 channels: returns 1 only if ch1 > ch0 (first-max tie rule)
    float qa = (qbg[(b * 2 + 1) * NHW + q] > qbg[(b * 2 + 0) * NHW + q]) ? 1.f : 0.f;
    float sa = (sbg[(b * 2 + 1) * NHW + q] > sbg[(b * 2 + 0) * NHW + q]) ? 1.f : 0.f;
    g_Ql[idx]   = ql;
    g_Qdis[idx] = fmaxf(1.f - qa - ql, 0.f);
    g_Sdis[idx] = fmaxf(1.f - sa - sl, 0.f);

    const float* Qp = Qf + (size_t)b * NC * NHW + q;
    const float* Sp = Sf + (size_t)b * NC * NHW + q;
    float sq = 0.f, ss = 0.f;
#pragma unroll 8
    for (int c = 0; c < NC; c++) {
        float v = Qp[(size_t)c * NHW]; sq += v * v;
        float u = Sp[(size_t)c * NHW]; ss += u * u;
    }
    g_qinv[idx] = (sq > 0.f) ? 1.f / sqrtf(sq) : 0.f;
    g_winv[idx] = (sl != 0.f && ss > 0.f) ? 1.f / sqrtf(ss) : 0.f;
    g_sim[idx] = 0;                                     // == 0.0f
}

// ---------------- K2: negatives output + bf16 operand packing ----------------
// Block: 32x32 (c x q) tile of one batch. Threads 32x8.
__global__ void k_pack(const float* __restrict__ Qf, const float* __restrict__ Sf,
                       float* __restrict__ neg, int write_neg)
{
    __shared__ float Qt[32][33];
    __shared__ float St[32][33];
    int b  = blockIdx.z;
    int q0 = blockIdx.x * 32;
    int c0 = blockIdx.y * 32;
    int tx = threadIdx.x, ty = threadIdx.y;

    const float* Qbase = Qf + ((size_t)b * NC + c0) * NHW + q0;
    const float* Sbase = Sf + ((size_t)b * NC + c0) * NHW + q0;
#pragma unroll
    for (int r = 0; r < 4; r++) {
        int c = ty + r * 8;
        Qt[c][tx] = Qbase[(size_t)c * NHW + tx];
        St[c][tx] = Sbase[(size_t)c * NHW + tx];
    }
    __syncthreads();

    if (write_neg) {
#pragma unroll
        for (int r = 0; r < 4; r++) {
            int ql = ty + r * 8;
            int q  = q0 + ql;
            float qd = g_Qdis[b * NHW + q];
            float sd = g_Sdis[b * NHW + q];
            neg[(((size_t)b * 2 + 0) * NHW + q) * NC + c0 + tx] = Qt[tx][ql] * qd;
            neg[(((size_t)b * 2 + 1) * NHW + q) * NC + c0 + tx] = St[tx][ql] * sd;
        }
    }
    // B operand: [b][kp][q]  (kp = c/2 pairs)
#pragma unroll
    for (int r = 0; r < 2; r++) {
        int kpl = ty + r * 8;  // 0..15
        g_Bm[((size_t)b * (NC / 2) + (c0 / 2 + kpl)) * NHW + q0 + tx] =
            packbf2(Qt[2 * kpl][tx], Qt[2 * kpl + 1][tx]);
    }
    // A operand: [b][s][kp], pre-scaled by Sl/|S_col|
    int tid = ty * 32 + tx;
#pragma unroll
    for (int r = 0; r < 2; r++) {
        int ent = tid + r * 256;
        int sl  = ent >> 4;       // 0..31
        int kpl = ent & 15;       // 0..15
        float wv = g_winv[b * NHW + q0 + sl];
        g_A[((size_t)b * NHW + q0 + sl) * (NC / 2) + c0 / 2 + kpl] =
            packbf2(St[2 * kpl][sl] * wv, St[2 * kpl + 1][sl] * wv);
    }
}

// ---------------- K3: bf16 mma GEMM (128x128 tile, K=256) + fused row-max ----------------
__global__ void __launch_bounds__(256, 2) k_gemm()
{
    __shared__ uint32_t As[128 * 12];   // [s][kp 0..7], stride 12 (conflict-free frag loads)
    __shared__ uint32_t Bs[8 * 136];    // [kp][q 0..127], stride 136

    int b  = blockIdx.z;
    int qt = blockIdx.x;   // N (query) tile
    int st = blockIdx.y;   // M (support) tile
    int tid  = threadIdx.x;
    int warp = tid >> 5, lane = tid & 31;
    int wm = warp >> 2, wn = warp & 3;      // 2x4 warp grid -> 64x32 warp tiles
    int g = lane >> 2, tc = lane & 3;

    float acc[4][4][4];
#pragma unroll
    for (int mi = 0; mi < 4; mi++)
#pragma unroll
        for (int ni = 0; ni < 4; ni++)
#pragma unroll
            for (int r = 0; r < 4; r++) acc[mi][ni][r] = 0.f;

    const uint4* gA = (const uint4*)(g_A + ((size_t)b * NHW + (size_t)st * 128) * (NC / 2));
    const uint4* gB = (const uint4*)(g_Bm + (size_t)b * (NC / 2) * NHW + (size_t)qt * 128);

    int sA = tid >> 1, pA = tid & 1;        // A loader: 2 threads/row, 1 uint4 each
    int kB = tid >> 5, jB = lane;           // B loader: 1 warp/row, 32x uint4

    uint4 va = gA[(size_t)sA * 32 + pA];                  // kp0 = 0 stage
    uint4 vb = gB[(size_t)kB * (NHW / 4) + jB];

#pragma unroll 1
    for (int kk = 0; kk < 16; kk++) {
        *(uint4*)&As[sA * 12 + pA * 4] = va;
        *(uint4*)&Bs[kB * 136 + jB * 4] = vb;
        __syncthreads();

        if (kk < 15) {                                    // prefetch next stage
            int kp0 = (kk + 1) * 8;
            va = gA[(size_t)sA * 32 + (kp0 >> 2) + pA];
            vb = gB[(size_t)(kp0 + kB) * (NHW / 4) + jB];
        }

        uint32_t af[4][4];
#pragma unroll
        for (int mi = 0; mi < 4; mi++) {
            int r0 = wm * 64 + mi * 16 + g;
            af[mi][0] = As[r0 * 12 + tc];
            af[mi][1] = As[(r0 + 8) * 12 + tc];
            af[mi][2] = As[r0 * 12 + tc + 4];
            af[mi][3] = As[(r0 + 8) * 12 + tc + 4];
        }
        uint32_t bfr[4][2];
#pragma unroll
        for (int ni = 0; ni < 4; ni++) {
            int n0 = wn * 32 + ni * 8 + g;
            bfr[ni][0] = Bs[tc * 136 + n0];
            bfr[ni][1] = Bs[(tc + 4) * 136 + n0];
        }
#pragma unroll
        for (int mi = 0; mi < 4; mi++)
#pragma unroll
            for (int ni = 0; ni < 4; ni++) {
                asm volatile(
                    "mma.sync.aligned.m16n8k16.row.col.f32.bf16.bf16.f32 "
                    "{%0,%1,%2,%3}, {%4,%5,%6,%7}, {%8,%9}, {%0,%1,%2,%3};"
                    : "+f"(acc[mi][ni][0]), "+f"(acc[mi][ni][1]),
                      "+f"(acc[mi][ni][2]), "+f"(acc[mi][ni][3])
                    : "r"(af[mi][0]), "r"(af[mi][1]), "r"(af[mi][2]), "r"(af[mi][3]),
                      "r"(bfr[ni][0]), "r"(bfr[ni][1]));
            }
        __syncthreads();
    }

    // fused column-max over this block's 128 support rows (clamped at 0 = zero-row value)
#pragma unroll
    for (int ni = 0; ni < 4; ni++) {
        float mA = acc[0][ni][0], mB = acc[0][ni][1];     // cols 2tc, 2tc+1
#pragma unroll
        for (int mi = 0; mi < 4; mi++) {
            mA = fmaxf(mA, fmaxf(acc[mi][ni][0], acc[mi][ni][2]));
            mB = fmaxf(mB, fmaxf(acc[mi][ni][1], acc[mi][ni][3]));
        }
#pragma unroll
        for (int off = 16; off >= 4; off >>= 1) {         // reduce over g (lane stride 4)
            mA = fmaxf(mA, __shfl_down_sync(0xffffffffu, mA, off));
            mB = fmaxf(mB, __shfl_down_sync(0xffffffffu, mB, off));
        }
        if (lane < 4) {
            int col = qt * 128 + wn * 32 + ni * 8 + 2 * tc;
            int* dst = g_sim + b * NHW + col;
            atomicMax(dst,     __float_as_int(fmaxf(mA, 0.f)));   // non-neg: int order == float order
            atomicMax(dst + 1, __float_as_int(fmaxf(mB, 0.f)));
        }
    }
}

// ---------------- K4: masked mean + log loss ----------------
__global__ void k_final(float* __restrict__ out)
{
    __shared__ float rs[256];
    __shared__ float rc[256];
    int tid = threadIdx.x;
    float total = 0.f;
    for (int b = 0; b < NB; b++) {
        float s = 0.f, c = 0.f;
        for (int i = tid; i < NHW; i += 256) {
            float m = g_Ql[b * NHW + i];
            if (m == 1.0f) {
                s += __int_as_float(g_sim[b * NHW + i]) * g_qinv[b * NHW + i];
                c += 1.f;
            }
        }
        rs[tid] = s; rc[tid] = c;
        __syncthreads();
        for (int off = 128; off > 0; off >>= 1) {
            if (tid < off) { rs[tid] += rs[tid + off]; rc[tid] += rc[tid + off]; }
            __syncthreads();
        }
        if (tid == 0) {
            float pc = 0.5f * (rs[0] / fmaxf(rc[0], 1.f) + 1.f);
            total += -logf(pc + 1e-8f);
        }
        __syncthreads();
    }
    if (tid == 0) out[0] = total * (1.f / NB);
}

// ---------------- launch ----------------
extern "C" void kernel_launch(void* const* d_in, const int* in_sizes, int n_in,
                              void* d_out, int out_size)
{
    const float* Qf   = (const float*)d_in[0];
    const float* Sf   = (const float*)d_in[1];
    const float* Qlab = (const float*)d_in[3];
    const float* Slab = (const float*)d_in[4];
    const float* qbg  = (const float*)d_in[5];
    const float* sbg  = (const float*)d_in[6];
    float* out = (float*)d_out;

    int write_neg = (out_size >= 1 + NB * 2 * NHW * NC) ? 1 : 0;

    k_prep<<<NB * NHW / 256, 256>>>(Qf, Sf, Qlab, Slab, qbg, sbg);
    k_pack<<<dim3(NHW / 32, NC / 32, NB), dim3(32, 8)>>>(Qf, Sf, out + 1, write_neg);
    k_gemm<<<dim3(NHW / 128, NHW / 128, NB), 256>>>();
    k_final<<<1, 256>>>(out);
}

// round 2
// speedup vs baseline: 2.2551x; 2.2551x over previous
#include <cuda_runtime.h>
#include <cuda_bf16.h>
#include <stdint.h>

#define NB 4
#define NC 256
#define NHW 4096
#define NL 512

// ---------------- scratch (no allocations allowed) ----------------
__device__ float    g_Ql   [NB*NHW];
__device__ float    g_Qdis [NB*NHW];
__device__ float    g_Sdis [NB*NHW];
__device__ float    g_winv [NB*NHW];          // Sl/|S_col| (0 if Sl==0)
__device__ float    g_qinv [NB*NHW];          // 1/|Q_col|
__device__ float    g_qinvc[NB*NHW];          // compacted qinv
__device__ int      g_qdest[NB*NHW];          // compacted col index or -1
__device__ int      g_sdest[NB*NHW];          // compacted row index or -1
__device__ int      g_nq[NB], g_ns[NB];
__device__ int      g_sim  [NB*NHW];          // float bits (non-neg), compacted space
__device__ float    g_lossb[NB];
__device__ uint32_t g_Ac[NB*NHW*(NC/2)];      // bf16x2: [b][i][kp], compacted support rows (8MB)
__device__ uint32_t g_Bc[NB*(NC/2)*NHW];      // bf16x2: [b][kp][j], compacted query cols  (8MB)

static __device__ __forceinline__ uint32_t packbf2(float lo, float hi) {
    __nv_bfloat162 t = __floats2bfloat162_rn(lo, hi);
    return *reinterpret_cast<uint32_t*>(&t);
}

// ---------------- K1: labels, disrupt masks, column norms ----------------
__global__ void k_prep(const float* __restrict__ Qf, const float* __restrict__ Sf,
                       const float* __restrict__ Qlab, const float* __restrict__ Slab,
                       const float* __restrict__ qbg, const float* __restrict__ sbg)
{
    int idx = blockIdx.x * blockDim.x + threadIdx.x;    // NB*NHW threads
    int b = idx >> 12;
    int q = idx & (NHW - 1);
    int h = q >> 6, w = q & 63;
    int lab = (h * 8) * NL + (w * 8);                   // nearest resize 512->64
    float ql = Qlab[b * NL * NL + lab];
    float sl = Slab[b * NL * NL + lab];
    float qa = (qbg[(b * 2 + 1) * NHW + q] > qbg[(b * 2 + 0) * NHW + q]) ? 1.f : 0.f;
    float sa = (sbg[(b * 2 + 1) * NHW + q] > sbg[(b * 2 + 0) * NHW + q]) ? 1.f : 0.f;
    g_Ql[idx]   = ql;
    g_Qdis[idx] = fmaxf(1.f - qa - ql, 0.f);
    g_Sdis[idx] = fmaxf(1.f - sa - sl, 0.f);

    const float* Qp = Qf + (size_t)b * NC * NHW + q;
    const float* Sp = Sf + (size_t)b * NC * NHW + q;
    float sq = 0.f, ss = 0.f;
#pragma unroll 8
    for (int c = 0; c < NC; c++) {
        float v = Qp[(size_t)c * NHW]; sq += v * v;
        float u = Sp[(size_t)c * NHW]; ss += u * u;
    }
    g_qinv[idx] = (sq > 0.f) ? 1.f / sqrtf(sq) : 0.f;
    g_winv[idx] = (sl != 0.f && ss > 0.f) ? 1.f / sqrtf(ss) : 0.f;
}

// ---------------- K2: deterministic per-batch compaction maps + pad/sim init ----------------
__global__ void k_compact()
{
    __shared__ int sq[1024];
    __shared__ int ss[1024];
    int b = blockIdx.x, tid = threadIdx.x;
    int base = b * NHW;

    int qf[4], sf[4];
    int lq = 0, ls = 0;
#pragma unroll
    for (int r = 0; r < 4; r++) {
        int idx = tid * 4 + r;
        qf[r] = (g_Ql[base + idx] == 1.0f);
        sf[r] = (g_winv[base + idx] > 0.f);
        lq += qf[r]; ls += sf[r];
    }
    sq[tid] = lq; ss[tid] = ls;
    __syncthreads();
    for (int off = 1; off < 1024; off <<= 1) {
        int a = (tid >= off) ? sq[tid - off] : 0;
        int c = (tid >= off) ? ss[tid - off] : 0;
        __syncthreads();
        sq[tid] += a; ss[tid] += c;
        __syncthreads();
    }
    int qex = sq[tid] - lq, sex = ss[tid] - ls;
#pragma unroll
    for (int r = 0; r < 4; r++) {
        int idx = tid * 4 + r;
        if (qf[r]) { g_qdest[base + idx] = qex; g_qinvc[base + qex] = g_qinv[base + idx]; }
        else         g_qdest[base + idx] = -1;
        if (sf[r])   g_sdest[base + idx] = sex;
        else         g_sdest[base + idx] = -1;
        qex += qf[r]; sex += sf[r];
    }
    int nq = sq[1023], ns = ss[1023];
    if (tid == 0) { g_nq[b] = nq; g_ns[b] = ns; }

    // zero sim (compacted space)
    for (int i = tid; i < NHW; i += 1024) g_sim[base + i] = 0;

    // zero A pad rows [ns, ceil128(ns)) : 128 u32 each
    int nsp = (ns + 127) & ~127;
    for (int i = tid; i < (nsp - ns) * 128; i += 1024) {
        int row = ns + (i >> 7), kp = i & 127;
        g_Ac[((size_t)base + row) * 128 + kp] = 0;
    }
    // zero B pad cols [nq, ceil128(nq)) for all 128 kp
    int nqp = (nq + 127) & ~127;
    int zc = nqp - nq;
    for (int i = tid; i < zc * 128; i += 1024) {
        int kp = i / zc, j = nq + i % zc;
        g_Bc[((size_t)b * 128 + kp) * NHW + j] = 0;
    }
}

// ---------------- K3: negatives + compacted bf16 operand packing ----------------
__global__ void k_pack(const float* __restrict__ Qf, const float* __restrict__ Sf,
                       float* __restrict__ neg, int write_neg)
{
    __shared__ float Qt[32][33];
    __shared__ float St[32][33];
    int b  = blockIdx.z;
    int q0 = blockIdx.x * 32;
    int c0 = blockIdx.y * 32;
    int tx = threadIdx.x, ty = threadIdx.y;

    const float* Qbase = Qf + ((size_t)b * NC + c0) * NHW + q0;
    const float* Sbase = Sf + ((size_t)b * NC + c0) * NHW + q0;
#pragma unroll
    for (int r = 0; r < 4; r++) {
        int c = ty + r * 8;
        Qt[c][tx] = Qbase[(size_t)c * NHW + tx];
        St[c][tx] = Sbase[(size_t)c * NHW + tx];
    }
    __syncthreads();

    if (write_neg) {
#pragma unroll
        for (int r = 0; r < 4; r++) {
            int ql = ty + r * 8;
            int q  = q0 + ql;
            float qd = g_Qdis[b * NHW + q];
            float sd = g_Sdis[b * NHW + q];
            neg[(((size_t)b * 2 + 0) * NHW + q) * NC + c0 + tx] = Qt[tx][ql] * qd;
            neg[(((size_t)b * 2 + 1) * NHW + q) * NC + c0 + tx] = St[tx][ql] * sd;
        }
    }
    // B operand (compacted cols): [b][kp][j]
    {
        int q = q0 + tx;
        int j = g_qdest[b * NHW + q];
        if (j >= 0) {
#pragma unroll
            for (int r = 0; r < 2; r++) {
                int kpl = ty + r * 8;  // 0..15
                g_Bc[((size_t)b * 128 + (c0 / 2 + kpl)) * NHW + j] =
                    packbf2(Qt[2 * kpl][tx], Qt[2 * kpl + 1][tx]);
            }
        }
    }
    // A operand (compacted rows, pre-scaled by Sl/|S_col|): [b][i][kp]
    int tid = ty * 32 + tx;
#pragma unroll
    for (int r = 0; r < 2; r++) {
        int ent = tid + r * 256;
        int sl  = ent >> 4;       // 0..31
        int kpl = ent & 15;       // 0..15
        int s = q0 + sl;
        int i = g_sdest[b * NHW + s];
        if (i >= 0) {
            float wv = g_winv[b * NHW + s];
            g_Ac[((size_t)b * NHW + i) * 128 + c0 / 2 + kpl] =
                packbf2(St[2 * kpl][sl] * wv, St[2 * kpl + 1][sl] * wv);
        }
    }
}

// ---------------- K4: bf16 mma GEMM (128x128 tile, K=256) + fused row-max ----------------
__global__ void __launch_bounds__(256, 2) k_gemm()
{
    __shared__ uint32_t As[128 * 12];   // [s][kp 0..7], stride 12
    __shared__ uint32_t Bs[8 * 136];    // [kp][q 0..127], stride 136

    int b  = blockIdx.z;
    int qt = blockIdx.x;   // N (compacted query) tile
    int st = blockIdx.y;   // M (compacted support) tile
    if (st * 128 >= g_ns[b] || qt * 128 >= g_nq[b]) return;   // early-exit padding grid

    int tid  = threadIdx.x;
    int warp = tid >> 5, lane = tid & 31;
    int wm = warp >> 2, wn = warp & 3;      // 2x4 warps -> 64x32 warp tiles
    int g = lane >> 2, tc = lane & 3;

    float acc[4][4][4];
#pragma unroll
    for (int mi = 0; mi < 4; mi++)
#pragma unroll
        for (int ni = 0; ni < 4; ni++)
#pragma unroll
            for (int r = 0; r < 4; r++) acc[mi][ni][r] = 0.f;

    const uint4* gA = (const uint4*)(g_Ac + ((size_t)b * NHW + (size_t)st * 128) * 128);
    const uint4* gB = (const uint4*)(g_Bc + (size_t)b * 128 * NHW + (size_t)qt * 128);

    int sA = tid >> 1, pA = tid & 1;        // A loader: 2 threads/row
    int kB = tid >> 5, jB = lane;           // B loader: 1 warp/row

    uint4 va = gA[(size_t)sA * 32 + pA];
    uint4 vb = gB[(size_t)kB * (NHW / 4) + jB];

#pragma unroll 1
    for (int kk = 0; kk < 16; kk++) {
        *(uint4*)&As[sA * 12 + pA * 4] = va;
        *(uint4*)&Bs[kB * 136 + jB * 4] = vb;
        __syncthreads();

        if (kk < 15) {
            int kp0 = (kk + 1) * 8;
            va = gA[(size_t)sA * 32 + (kp0 >> 2) + pA];
            vb = gB[(size_t)(kp0 + kB) * (NHW / 4) + jB];
        }

        uint32_t af[4][4];
#pragma unroll
        for (int mi = 0; mi < 4; mi++) {
            int r0 = wm * 64 + mi * 16 + g;
            af[mi][0] = As[r0 * 12 + tc];
            af[mi][1] = As[(r0 + 8) * 12 + tc];
            af[mi][2] = As[r0 * 12 + tc + 4];
            af[mi][3] = As[(r0 + 8) * 12 + tc + 4];
        }
        uint32_t bfr[4][2];
#pragma unroll
        for (int ni = 0; ni < 4; ni++) {
            int n0 = wn * 32 + ni * 8 + g;
            bfr[ni][0] = Bs[tc * 136 + n0];
            bfr[ni][1] = Bs[(tc + 4) * 136 + n0];
        }
#pragma unroll
        for (int mi = 0; mi < 4; mi++)
#pragma unroll
            for (int ni = 0; ni < 4; ni++) {
                asm volatile(
                    "mma.sync.aligned.m16n8k16.row.col.f32.bf16.bf16.f32 "
                    "{%0,%1,%2,%3}, {%4,%5,%6,%7}, {%8,%9}, {%0,%1,%2,%3};"
                    : "+f"(acc[mi][ni][0]), "+f"(acc[mi][ni][1]),
                      "+f"(acc[mi][ni][2]), "+f"(acc[mi][ni][3])
                    : "r"(af[mi][0]), "r"(af[mi][1]), "r"(af[mi][2]), "r"(af[mi][3]),
                      "r"(bfr[ni][0]), "r"(bfr[ni][1]));
            }
        __syncthreads();
    }

    // fused column-max over this block's 128 support rows (clamped at 0)
#pragma unroll
    for (int ni = 0; ni < 4; ni++) {
        float mA = acc[0][ni][0], mB = acc[0][ni][1];
#pragma unroll
        for (int mi = 0; mi < 4; mi++) {
            mA = fmaxf(mA, fmaxf(acc[mi][ni][0], acc[mi][ni][2]));
            mB = fmaxf(mB, fmaxf(acc[mi][ni][1], acc[mi][ni][3]));
        }
#pragma unroll
        for (int off = 16; off >= 4; off >>= 1) {
            mA = fmaxf(mA, __shfl_down_sync(0xffffffffu, mA, off));
            mB = fmaxf(mB, __shfl_down_sync(0xffffffffu, mB, off));
        }
        if (lane < 4) {
            int col = qt * 128 + wn * 32 + ni * 8 + 2 * tc;
            int* dst = g_sim + b * NHW + col;
            atomicMax(dst,     __float_as_int(fmaxf(mA, 0.f)));
            atomicMax(dst + 1, __float_as_int(fmaxf(mB, 0.f)));
        }
    }
}

// ---------------- K5: per-batch masked mean + log ----------------
__global__ void k_loss()
{
    __shared__ float rs[256];
    int b = blockIdx.x, tid = threadIdx.x;
    int nq = g_nq[b];
    float s = 0.f;
    for (int j = tid; j < nq; j += 256)
        s += __int_as_float(g_sim[b * NHW + j]) * g_qinvc[b * NHW + j];
    rs[tid] = s;
    __syncthreads();
    for (int off = 128; off > 0; off >>= 1) {
        if (tid < off) rs[tid] += rs[tid + off];
        __syncthreads();
    }
    if (tid == 0) {
        float pc = 0.5f * (rs[0] / fmaxf((float)nq, 1.f) + 1.f);
        g_lossb[b] = -logf(pc + 1e-8f);
    }
}

__global__ void k_out(float* __restrict__ out)
{
    if (threadIdx.x == 0)
        out[0] = 0.25f * (g_lossb[0] + g_lossb[1] + g_lossb[2] + g_lossb[3]);
}

// ---------------- launch ----------------
extern "C" void kernel_launch(void* const* d_in, const int* in_sizes, int n_in,
                              void* d_out, int out_size)
{
    const float* Qf   = (const float*)d_in[0];
    const float* Sf   = (const float*)d_in[1];
    const float* Qlab = (const float*)d_in[3];
    const float* Slab = (const float*)d_in[4];
    const float* qbg  = (const float*)d_in[5];
    const float* sbg  = (const float*)d_in[6];
    float* out = (float*)d_out;

    int write_neg = (out_size >= 1 + NB * 2 * NHW * NC) ? 1 : 0;

    k_prep<<<NB * NHW / 256, 256>>>(Qf, Sf, Qlab, Slab, qbg, sbg);
    k_compact<<<NB, 1024>>>();
    k_pack<<<dim3(NHW / 32, NC / 32, NB), dim3(32, 8)>>>(Qf, Sf, out + 1, write_neg);
    k_gemm<<<dim3(NHW / 128, NHW / 128, NB), 256>>>();
    k_loss<<<NB, 256>>>();
    k_out<<<1, 32>>>(out);
}

// round 5
// speedup vs baseline: 2.4502x; 1.0865x over previous
#include <cuda_runtime.h>
#include <cuda_bf16.h>
#include <stdint.h>

#define NB 4
#define NC 256
#define NHW 4096
#define NL 512

// ---------------- scratch (no allocations allowed) ----------------
__device__ float    g_Ql   [NB*NHW];
__device__ float    g_Qdis [NB*NHW];
__device__ float    g_Sdis [NB*NHW];
__device__ float    g_winv [NB*NHW];
__device__ float    g_qinv [NB*NHW];
__device__ float    g_qinvc[NB*NHW];
__device__ int      g_qdest[NB*NHW];
__device__ int      g_sdest[NB*NHW];
__device__ int      g_nq[NB], g_ns[NB];
__device__ int      g_sim  [NB*NHW];
__device__ float    g_lossb[NB];
__device__ uint32_t g_Ac[NB*NHW*(NC/2)];      // bf16: [b][i][k] row-major (compacted support)
__device__ uint32_t g_Bc[NB*NHW*(NC/2)];      // bf16: [b][j][k] row-major (compacted query)

static __device__ __forceinline__ uint32_t packbf2(float lo, float hi) {
    __nv_bfloat162 t = __floats2bfloat162_rn(lo, hi);
    return *reinterpret_cast<uint32_t*>(&t);
}

#define CP_ASYNC16(dst, src) \
    asm volatile("cp.async.cg.shared.global [%0], [%1], 16;\n" :: "r"(dst), "l"(src))
#define CP_COMMIT() asm volatile("cp.async.commit_group;\n")
#define CP_WAIT1()  asm volatile("cp.async.wait_group 1;\n")
#define CP_WAIT0()  asm volatile("cp.async.wait_group 0;\n")

// ---------------- K1: labels, disrupt masks, column norms ----------------
__global__ void k_prep(const float* __restrict__ Qf, const float* __restrict__ Sf,
                       const float* __restrict__ Qlab, const float* __restrict__ Slab,
                       const float* __restrict__ qbg, const float* __restrict__ sbg)
{
    int idx = blockIdx.x * blockDim.x + threadIdx.x;
    int b = idx >> 12;
    int q = idx & (NHW - 1);
    int h = q >> 6, w = q & 63;
    int lab = (h * 8) * NL + (w * 8);
    float ql = Qlab[b * NL * NL + lab];
    float sl = Slab[b * NL * NL + lab];
    float qa = (qbg[(b * 2 + 1) * NHW + q] > qbg[(b * 2 + 0) * NHW + q]) ? 1.f : 0.f;
    float sa = (sbg[(b * 2 + 1) * NHW + q] > sbg[(b * 2 + 0) * NHW + q]) ? 1.f : 0.f;
    g_Ql[idx]   = ql;
    g_Qdis[idx] = fmaxf(1.f - qa - ql, 0.f);
    g_Sdis[idx] = fmaxf(1.f - sa - sl, 0.f);

    const float* Qp = Qf + (size_t)b * NC * NHW + q;
    const float* Sp = Sf + (size_t)b * NC * NHW + q;
    float sq = 0.f, ss = 0.f;
#pragma unroll 8
    for (int c = 0; c < NC; c++) {
        float v = Qp[(size_t)c * NHW]; sq += v * v;
        float u = Sp[(size_t)c * NHW]; ss += u * u;
    }
    g_qinv[idx] = (sq > 0.f) ? 1.f / sqrtf(sq) : 0.f;
    g_winv[idx] = (sl != 0.f && ss > 0.f) ? 1.f / sqrtf(ss) : 0.f;
}

// ---------------- K2: deterministic per-batch compaction + pad/sim init ----------------
__global__ void k_compact()
{
    __shared__ int sq[1024];
    __shared__ int ss[1024];
    int b = blockIdx.x, tid = threadIdx.x;
    int base = b * NHW;

    int qf[4], sf[4];
    int lq = 0, ls = 0;
#pragma unroll
    for (int r = 0; r < 4; r++) {
        int idx = tid * 4 + r;
        qf[r] = (g_Ql[base + idx] == 1.0f);
        sf[r] = (g_winv[base + idx] > 0.f);
        lq += qf[r]; ls += sf[r];
    }
    sq[tid] = lq; ss[tid] = ls;
    __syncthreads();
    for (int off = 1; off < 1024; off <<= 1) {
        int a = (tid >= off) ? sq[tid - off] : 0;
        int c = (tid >= off) ? ss[tid - off] : 0;
        __syncthreads();
        sq[tid] += a; ss[tid] += c;
        __syncthreads();
    }
    int qex = sq[tid] - lq, sex = ss[tid] - ls;
#pragma unroll
    for (int r = 0; r < 4; r++) {
        int idx = tid * 4 + r;
        if (qf[r]) { g_qdest[base + idx] = qex; g_qinvc[base + qex] = g_qinv[base + idx]; }
        else         g_qdest[base + idx] = -1;
        if (sf[r])   g_sdest[base + idx] = sex;
        else         g_sdest[base + idx] = -1;
        qex += qf[r]; sex += sf[r];
    }
    int nq = sq[1023], ns = ss[1023];
    if (tid == 0) { g_nq[b] = nq; g_ns[b] = ns; }

    for (int i = tid; i < NHW; i += 1024) g_sim[base + i] = 0;

    // zero A pad rows [ns, ceil128(ns)) and B pad rows [nq, ceil128(nq)) : 128 u32 each
    int nsp = (ns + 127) & ~127;
    for (int i = tid; i < (nsp - ns) * 128; i += 1024) {
        int row = ns + (i >> 7), kp = i & 127;
        g_Ac[((size_t)base + row) * 128 + kp] = 0;
    }
    int nqp = (nq + 127) & ~127;
    for (int i = tid; i < (nqp - nq) * 128; i += 1024) {
        int row = nq + (i >> 7), kp = i & 127;
        g_Bc[((size_t)base + row) * 128 + kp] = 0;
    }
}

// ---------------- K3: negatives + compacted bf16 operand packing ----------------
__global__ void k_pack(const float* __restrict__ Qf, const float* __restrict__ Sf,
                       float* __restrict__ neg, int write_neg)
{
    __shared__ float Qt[32][33];
    __shared__ float St[32][33];
    int b  = blockIdx.z;
    int q0 = blockIdx.x * 32;
    int c0 = blockIdx.y * 32;
    int tx = threadIdx.x, ty = threadIdx.y;

    const float* Qbase = Qf + ((size_t)b * NC + c0) * NHW + q0;
    const float* Sbase = Sf + ((size_t)b * NC + c0) * NHW + q0;
#pragma unroll
    for (int r = 0; r < 4; r++) {
        int c = ty + r * 8;
        Qt[c][tx] = Qbase[(size_t)c * NHW + tx];
        St[c][tx] = Sbase[(size_t)c * NHW + tx];
    }
    __syncthreads();

    if (write_neg) {
#pragma unroll
        for (int r = 0; r < 4; r++) {
            int ql = ty + r * 8;
            int q  = q0 + ql;
            float qd = g_Qdis[b * NHW + q];
            float sd = g_Sdis[b * NHW + q];
            neg[(((size_t)b * 2 + 0) * NHW + q) * NC + c0 + tx] = Qt[tx][ql] * qd;
            neg[(((size_t)b * 2 + 1) * NHW + q) * NC + c0 + tx] = St[tx][ql] * sd;
        }
    }
    int tid = ty * 32 + tx;
    // B operand: [b][j][kp], coalesced 16 threads/row
#pragma unroll
    for (int r = 0; r < 2; r++) {
        int ent = tid + r * 256;
        int sl  = ent >> 4;
        int kpl = ent & 15;
        int j = g_qdest[b * NHW + q0 + sl];
        if (j >= 0) {
            g_Bc[((size_t)b * NHW + j) * 128 + c0 / 2 + kpl] =
                packbf2(Qt[2 * kpl][sl], Qt[2 * kpl + 1][sl]);
        }
    }
    // A operand: [b][i][kp], pre-scaled by Sl/|S_col|
#pragma unroll
    for (int r = 0; r < 2; r++) {
        int ent = tid + r * 256;
        int sl  = ent >> 4;
        int kpl = ent & 15;
        int i = g_sdest[b * NHW + q0 + sl];
        if (i >= 0) {
            float wv = g_winv[b * NHW + q0 + sl];
            g_Ac[((size_t)b * NHW + i) * 128 + c0 / 2 + kpl] =
                packbf2(St[2 * kpl][sl] * wv, St[2 * kpl + 1][sl] * wv);
        }
    }
}

// ---------------- K4: ldmatrix + cp.async double-buffered bf16 mma GEMM ----------------
// Tile 128x128, K=256 in 8 stages of 32 k (4 uint4 chunks/row).
// smem: [buf][row][slot] with slot = (chunk + (row>>1)) & 3  (conflict-free for LDSM)
__global__ void __launch_bounds__(256, 2) k_gemm()
{
    __shared__ uint4 As[2][128][4];   // 8KB per buffer
    __shared__ uint4 Bs[2][128][4];

    int b  = blockIdx.z;
    int qt = blockIdx.x;
    int st = blockIdx.y;
    if (st * 128 >= g_ns[b] || qt * 128 >= g_nq[b]) return;

    int tid  = threadIdx.x;
    int warp = tid >> 5, lane = tid & 31;
    int wm = warp >> 2, wn = warp & 3;      // 2x4 warps -> 64x32 warp tiles
    int g = lane >> 2, tc = lane & 3;

    float acc[4][4][4];
#pragma unroll
    for (int mi = 0; mi < 4; mi++)
#pragma unroll
        for (int ni = 0; ni < 4; ni++)
#pragma unroll
            for (int r = 0; r < 4; r++) acc[mi][ni][r] = 0.f;

    const uint4* gA = (const uint4*)(g_Ac + ((size_t)b * NHW + (size_t)st * 128) * 128);
    const uint4* gB = (const uint4*)(g_Bc + ((size_t)b * NHW + (size_t)qt * 128) * 128);

    uint32_t smA = (uint32_t)__cvta_generic_to_shared(&As[0][0][0]);
    uint32_t smB = (uint32_t)__cvta_generic_to_shared(&Bs[0][0][0]);

    // loader mapping: 2 threads/row, each 2 consecutive chunks (32B)
    int lrow = tid >> 1;
    int lcb  = (tid & 1) * 2;
    int lsw  = (lrow >> 1) & 3;
    const uint4* gArow = gA + (size_t)lrow * 32 + lcb;
    const uint4* gBrow = gB + (size_t)lrow * 32 + lcb;
    uint32_t sArow = smA + lrow * 64;
    uint32_t sBrow = smB + lrow * 64;

#define ISSUE_STAGE(s, buf) do {                                            \
        int _o = (buf) * 8192;                                              \
        CP_ASYNC16(sArow + _o + (((lcb + 0 + lsw) & 3) << 4), gArow + (s)*4 + 0); \
        CP_ASYNC16(sArow + _o + (((lcb + 1 + lsw) & 3) << 4), gArow + (s)*4 + 1); \
        CP_ASYNC16(sBrow + _o + (((lcb + 0 + lsw) & 3) << 4), gBrow + (s)*4 + 0); \
        CP_ASYNC16(sBrow + _o + (((lcb + 1 + lsw) & 3) << 4), gBrow + (s)*4 + 1); \
        CP_COMMIT();                                                        \
    } while (0)

    ISSUE_STAGE(0, 0);
    ISSUE_STAGE(1, 1);

    // LDSM thread->address precompute
    int mt = wm * 64 + (lane & 15);              // A: m row for this thread
    int akh = lane >> 4;                         // A: k-half select
    uint32_t aBase = smA + mt * 64;
    int aSw = (mt >> 1) & 3;
    int nt = wn * 32 + (lane & 7) + ((lane >> 4) & 1) * 8;   // B: n row
    int bkh = (lane >> 3) & 1;
    uint32_t bBase = smB + nt * 64;
    int bSw = (nt >> 1) & 3;

#pragma unroll 1
    for (int s = 0; s < 8; s++) {
        int buf = s & 1;
        if (s < 6) { CP_WAIT1(); } else { CP_WAIT0(); }
        __syncthreads();

        int bo = buf * 8192;
#pragma unroll
        for (int j = 0; j < 2; j++) {
            uint32_t aSlot = (uint32_t)(((2 * j + akh + aSw) & 3) << 4);
            uint32_t bSlot = (uint32_t)(((2 * j + bkh + bSw) & 3) << 4);
            uint32_t af[4][4];
#pragma unroll
            for (int mi = 0; mi < 4; mi++) {
                uint32_t addr = aBase + bo + mi * 1024 + aSlot;
                asm volatile("ldmatrix.sync.aligned.m8n8.x4.shared.b16 {%0,%1,%2,%3}, [%4];"
                             : "=r"(af[mi][0]), "=r"(af[mi][1]), "=r"(af[mi][2]), "=r"(af[mi][3])
                             : "r"(addr));
            }
            uint32_t bf[4][2];
#pragma unroll
            for (int p = 0; p < 2; p++) {
                uint32_t addr = bBase + bo + p * 1024 + bSlot;
                asm volatile("ldmatrix.sync.aligned.m8n8.x4.shared.b16 {%0,%1,%2,%3}, [%4];"
                             : "=r"(bf[2*p][0]), "=r"(bf[2*p][1]),
                               "=r"(bf[2*p+1][0]), "=r"(bf[2*p+1][1])
                             : "r"(addr));
            }
#pragma unroll
            for (int mi = 0; mi < 4; mi++)
#pragma unroll
                for (int ni = 0; ni < 4; ni++) {
                    asm volatile(
                        "mma.sync.aligned.m16n8k16.row.col.f32.bf16.bf16.f32 "
                        "{%0,%1,%2,%3}, {%4,%5,%6,%7}, {%8,%9}, {%0,%1,%2,%3};"
                        : "+f"(acc[mi][ni][0]), "+f"(acc[mi][ni][1]),
                          "+f"(acc[mi][ni][2]), "+f"(acc[mi][ni][3])
                        : "r"(af[mi][0]), "r"(af[mi][1]), "r"(af[mi][2]), "r"(af[mi][3]),
                          "r"(bf[ni][0]), "r"(bf[ni][1]));
                }
        }
        __syncthreads();
        if (s + 2 < 8) ISSUE_STAGE(s + 2, buf);
    }

    // fused column-max over this block's 128 support rows (clamped at 0)
#pragma unroll
    for (int ni = 0; ni < 4; ni++) {
        float mA = acc[0][ni][0], mB = acc[0][ni][1];
#pragma unroll
        for (int mi = 0; mi < 4; mi++) {
            mA = fmaxf(mA, fmaxf(acc[mi][ni][0], acc[mi][ni][2]));
            mB = fmaxf(mB, fmaxf(acc[mi][ni][1], acc[mi][ni][3]));
        }
#pragma unroll
        for (int off = 16; off >= 4; off >>= 1) {
            mA = fmaxf(mA, __shfl_down_sync(0xffffffffu, mA, off));
            mB = fmaxf(mB, __shfl_down_sync(0xffffffffu, mB, off));
        }
        if (lane < 4) {
            int col = qt * 128 + wn * 32 + ni * 8 + 2 * tc;
            int* dst = g_sim + b * NHW + col;
            atomicMax(dst,     __float_as_int(fmaxf(mA, 0.f)));
            atomicMax(dst + 1, __float_as_int(fmaxf(mB, 0.f)));
        }
    }
#undef ISSUE_STAGE
}

// ---------------- K5: per-batch masked mean + log ----------------
__global__ void k_loss()
{
    __shared__ float rs[256];
    int b = blockIdx.x, tid = threadIdx.x;
    int nq = g_nq[b];
    float s = 0.f;
    for (int j = tid; j < nq; j += 256)
        s += __int_as_float(g_sim[b * NHW + j]) * g_qinvc[b * NHW + j];
    rs[tid] = s;
    __syncthreads();
    for (int off = 128; off > 0; off >>= 1) {
        if (tid < off) rs[tid] += rs[tid + off];
        __syncthreads();
    }
    if (tid == 0) {
        float pc = 0.5f * (rs[0] / fmaxf((float)nq, 1.f) + 1.f);
        g_lossb[b] = -logf(pc + 1e-8f);
    }
}

__global__ void k_out(float* __restrict__ out)
{
    if (threadIdx.x == 0)
        out[0] = 0.25f * (g_lossb[0] + g_lossb[1] + g_lossb[2] + g_lossb[3]);
}

// ---------------- launch ----------------
extern "C" void kernel_launch(void* const* d_in, const int* in_sizes, int n_in,
                              void* d_out, int out_size)
{
    const float* Qf   = (const float*)d_in[0];
    const float* Sf   = (const float*)d_in[1];
    const float* Qlab = (const float*)d_in[3];
    const float* Slab = (const float*)d_in[4];
    const float* qbg  = (const float*)d_in[5];
    const float* sbg  = (const float*)d_in[6];
    float* out = (float*)d_out;

    int write_neg = (out_size >= 1 + NB * 2 * NHW * NC) ? 1 : 0;

    k_prep<<<NB * NHW / 256, 256>>>(Qf, Sf, Qlab, Slab, qbg, sbg);
    k_compact<<<NB, 1024>>>();
    k_pack<<<dim3(NHW / 32, NC / 32, NB), dim3(32, 8)>>>(Qf, Sf, out + 1, write_neg);
    k_gemm<<<dim3(NHW / 128, NHW / 128, NB), 256>>>();
    k_loss<<<NB, 256>>>();
    k_out<<<1, 32>>>(out);
}

// round 7
// speedup vs baseline: 2.8148x; 1.1488x over previous
#include <cuda_runtime.h>
#include <cuda_bf16.h>
#include <stdint.h>

#define NB 4
#define NC 256
#define NHW 4096
#define NL 512

// ---------------- scratch (no allocations allowed) ----------------
__device__ float    g_Ql   [NB*NHW];
__device__ float    g_Qdis [NB*NHW];
__device__ float    g_Sdis [NB*NHW];
__device__ float    g_winv [NB*NHW];
__device__ float    g_qinv [NB*NHW];
__device__ float    g_qinvc[NB*NHW];
__device__ int      g_qdest[NB*NHW];
__device__ int      g_sdest[NB*NHW];
__device__ int      g_nq[NB], g_ns[NB];
__device__ int      g_sim  [NB*NHW];
__device__ float    g_lossb[NB];
__device__ uint32_t g_Ac[NB*NHW*(NC/2)];      // bf16: [b][i][k] row-major (compacted support, pre-scaled)
__device__ uint32_t g_Bc[NB*NHW*(NC/2)];      // bf16: [b][j][k] row-major (compacted query)

static __device__ __forceinline__ uint32_t packbf2(float lo, float hi) {
    __nv_bfloat162 t = __floats2bfloat162_rn(lo, hi);
    return *reinterpret_cast<uint32_t*>(&t);
}

#define CP_ASYNC16(dst, src) \
    asm volatile("cp.async.cg.shared.global [%0], [%1], 16;\n" :: "r"(dst), "l"(src))
#define CP_COMMIT() asm volatile("cp.async.commit_group;\n")
#define CP_WAIT1()  asm volatile("cp.async.wait_group 1;\n" ::: "memory")
#define CP_WAIT0()  asm volatile("cp.async.wait_group 0;\n" ::: "memory")

// ---------------- K1: labels, disrupt masks, column norms (parallel over C) ----------------
// Block: 32 pixels (tx) x 8 channel-slices (ty). 512 blocks total.
__global__ void k_prep(const float* __restrict__ Qf, const float* __restrict__ Sf,
                       const float* __restrict__ Qlab, const float* __restrict__ Slab,
                       const float* __restrict__ qbg, const float* __restrict__ sbg)
{
    __shared__ float sqs[8][33];
    __shared__ float sss[8][33];
    int blk = blockIdx.x;                  // NB*NHW/32 = 512
    int b   = blk >> 7;
    int q0  = (blk & 127) * 32;
    int tx  = threadIdx.x & 31, ty = threadIdx.x >> 5;
    int q   = q0 + tx;

    const float* Qp = Qf + ((size_t)b * NC + ty * 32) * NHW + q;
    const float* Sp = Sf + ((size_t)b * NC + ty * 32) * NHW + q;
    float sq = 0.f, ss = 0.f;
#pragma unroll
    for (int c = 0; c < 32; c++) {
        float v = Qp[(size_t)c * NHW]; sq += v * v;
        float u = Sp[(size_t)c * NHW]; ss += u * u;
    }
    sqs[ty][tx] = sq; sss[ty][tx] = ss;
    __syncthreads();

    if (ty == 0) {
        float tq = 0.f, ts = 0.f;
#pragma unroll
        for (int r = 0; r < 8; r++) { tq += sqs[r][tx]; ts += sss[r][tx]; }
        int idx = b * NHW + q;
        int h = q >> 6, w = q & 63;
        int lab = (h * 8) * NL + (w * 8);              // nearest resize 512->64
        float ql = Qlab[b * NL * NL + lab];
        float sl = Slab[b * NL * NL + lab];
        float qa = (qbg[(b * 2 + 1) * NHW + q] > qbg[(b * 2 + 0) * NHW + q]) ? 1.f : 0.f;
        float sa = (sbg[(b * 2 + 1) * NHW + q] > sbg[(b * 2 + 0) * NHW + q]) ? 1.f : 0.f;
        g_Ql[idx]   = ql;
        g_Qdis[idx] = fmaxf(1.f - qa - ql, 0.f);
        g_Sdis[idx] = fmaxf(1.f - sa - sl, 0.f);
        g_qinv[idx] = (tq > 0.f) ? 1.f / sqrtf(tq) : 0.f;
        g_winv[idx] = (sl != 0.f && ts > 0.f) ? 1.f / sqrtf(ts) : 0.f;
    }
}

// ---------------- K2: deterministic per-batch compaction + pad/sim init ----------------
__global__ void k_compact()
{
    __shared__ int sq[1024];
    __shared__ int ss[1024];
    int b = blockIdx.x, tid = threadIdx.x;
    int base = b * NHW;

    int qf[4], sf[4];
    int lq = 0, ls = 0;
#pragma unroll
    for (int r = 0; r < 4; r++) {
        int idx = tid * 4 + r;
        qf[r] = (g_Ql[base + idx] == 1.0f);
        sf[r] = (g_winv[base + idx] > 0.f);
        lq += qf[r]; ls += sf[r];
    }
    sq[tid] = lq; ss[tid] = ls;
    __syncthreads();
    for (int off = 1; off < 1024; off <<= 1) {
        int a = (tid >= off) ? sq[tid - off] : 0;
        int c = (tid >= off) ? ss[tid - off] : 0;
        __syncthreads();
        sq[tid] += a; ss[tid] += c;
        __syncthreads();
    }
    int qex = sq[tid] - lq, sex = ss[tid] - ls;
#pragma unroll
    for (int r = 0; r < 4; r++) {
        int idx = tid * 4 + r;
        if (qf[r]) { g_qdest[base + idx] = qex; g_qinvc[base + qex] = g_qinv[base + idx]; }
        else         g_qdest[base + idx] = -1;
        if (sf[r])   g_sdest[base + idx] = sex;
        else         g_sdest[base + idx] = -1;
        qex += qf[r]; sex += sf[r];
    }
    int nq = sq[1023], ns = ss[1023];
    if (tid == 0) { g_nq[b] = nq; g_ns[b] = ns; }

    for (int i = tid; i < NHW; i += 1024) g_sim[base + i] = 0;

    int nsp = (ns + 127) & ~127;
    for (int i = tid; i < (nsp - ns) * 128; i += 1024) {
        int row = ns + (i >> 7), kp = i & 127;
        g_Ac[((size_t)base + row) * 128 + kp] = 0;
    }
    int nqp = (nq + 127) & ~127;
    for (int i = tid; i < (nqp - nq) * 128; i += 1024) {
        int row = nq + (i >> 7), kp = i & 127;
        g_Bc[((size_t)base + row) * 128 + kp] = 0;
    }
}

// ---------------- K3: negatives + compacted bf16 operand packing ----------------
__global__ void k_pack(const float* __restrict__ Qf, const float* __restrict__ Sf,
                       float* __restrict__ neg, int write_neg)
{
    __shared__ float Qt[32][33];
    __shared__ float St[32][33];
    int b  = blockIdx.z;
    int q0 = blockIdx.x * 32;
    int c0 = blockIdx.y * 32;
    int tx = threadIdx.x, ty = threadIdx.y;

    const float* Qbase = Qf + ((size_t)b * NC + c0) * NHW + q0;
    const float* Sbase = Sf + ((size_t)b * NC + c0) * NHW + q0;
#pragma unroll
    for (int r = 0; r < 4; r++) {
        int c = ty + r * 8;
        Qt[c][tx] = Qbase[(size_t)c * NHW + tx];
        St[c][tx] = Sbase[(size_t)c * NHW + tx];
    }
    __syncthreads();

    if (write_neg) {
#pragma unroll
        for (int r = 0; r < 4; r++) {
            int ql = ty + r * 8;
            int q  = q0 + ql;
            float qd = g_Qdis[b * NHW + q];
            float sd = g_Sdis[b * NHW + q];
            neg[(((size_t)b * 2 + 0) * NHW + q) * NC + c0 + tx] = Qt[tx][ql] * qd;
            neg[(((size_t)b * 2 + 1) * NHW + q) * NC + c0 + tx] = St[tx][ql] * sd;
        }
    }
    int tid = ty * 32 + tx;
    // B operand: [b][j][kp] (compacted queries)
#pragma unroll
    for (int r = 0; r < 2; r++) {
        int ent = tid + r * 256;
        int sl  = ent >> 4;
        int kpl = ent & 15;
        int j = g_qdest[b * NHW + q0 + sl];
        if (j >= 0) {
            g_Bc[((size_t)b * NHW + j) * 128 + c0 / 2 + kpl] =
                packbf2(Qt[2 * kpl][sl], Qt[2 * kpl + 1][sl]);
        }
    }
    // A operand: [b][i][kp] (compacted support, pre-scaled by Sl/|S_col|)
#pragma unroll
    for (int r = 0; r < 2; r++) {
        int ent = tid + r * 256;
        int sl  = ent >> 4;
        int kpl = ent & 15;
        int i = g_sdest[b * NHW + q0 + sl];
        if (i >= 0) {
            float wv = g_winv[b * NHW + q0 + sl];
            g_Ac[((size_t)b * NHW + i) * 128 + c0 / 2 + kpl] =
                packbf2(St[2 * kpl][sl] * wv, St[2 * kpl + 1][sl] * wv);
        }
    }
}

// ---------------- K4: ldmatrix + 3-stage cp.async bf16 mma GEMM ----------------
// Tile 128x128, K=256 in 8 stages of 32 k. 3 smem buffers, ONE syncthreads/stage:
// at stage s (compute buf s%3), issue stage s+2 into buf (s+2)%3 == (s-1)%3,
// which all warps finished reading before this stage's barrier.
__global__ void __launch_bounds__(256, 2) k_gemm()
{
    __shared__ uint4 As[3][128][4];   // 8KB per buffer
    __shared__ uint4 Bs[3][128][4];

    int b  = blockIdx.z;
    int qt = blockIdx.x;
    int st = blockIdx.y;
    if (st * 128 >= g_ns[b] || qt * 128 >= g_nq[b]) return;

    int tid  = threadIdx.x;
    int warp = tid >> 5, lane = tid & 31;
    int wm = warp >> 2, wn = warp & 3;      // 2x4 warps -> 64x32 warp tiles
    int tc = lane & 3;

    float acc[4][4][4];
#pragma unroll
    for (int mi = 0; mi < 4; mi++)
#pragma unroll
        for (int ni = 0; ni < 4; ni++)
#pragma unroll
            for (int r = 0; r < 4; r++) acc[mi][ni][r] = 0.f;

    const uint4* gA = (const uint4*)(g_Ac + ((size_t)b * NHW + (size_t)st * 128) * 128);
    const uint4* gB = (const uint4*)(g_Bc + ((size_t)b * NHW + (size_t)qt * 128) * 128);

    uint32_t smA = (uint32_t)__cvta_generic_to_shared(&As[0][0][0]);
    uint32_t smB = (uint32_t)__cvta_generic_to_shared(&Bs[0][0][0]);

    // loader mapping: 2 threads/row, each 2 consecutive chunks (32B)
    int lrow = tid >> 1;
    int lcb  = (tid & 1) * 2;
    int lsw  = (lrow >> 1) & 3;
    const uint4* gArow = gA + (size_t)lrow * 32 + lcb;
    const uint4* gBrow = gB + (size_t)lrow * 32 + lcb;
    uint32_t sArow = smA + lrow * 64;
    uint32_t sBrow = smB + lrow * 64;

#define ISSUE_STAGE(s, buf) do {                                            \
        int _o = (buf) * 8192;                                              \
        CP_ASYNC16(sArow + _o + (((lcb + 0 + lsw) & 3) << 4), gArow + (s)*4 + 0); \
        CP_ASYNC16(sArow + _o + (((lcb + 1 + lsw) & 3) << 4), gArow + (s)*4 + 1); \
        CP_ASYNC16(sBrow + _o + (((lcb + 0 + lsw) & 3) << 4), gBrow + (s)*4 + 0); \
        CP_ASYNC16(sBrow + _o + (((lcb + 1 + lsw) & 3) << 4), gBrow + (s)*4 + 1); \
        CP_COMMIT();                                                        \
    } while (0)

    ISSUE_STAGE(0, 0);
    ISSUE_STAGE(1, 1);

    // LDSM thread->address precompute
    int mt = wm * 64 + (lane & 15);              // A: m row for this thread
    int akh = lane >> 4;                         // A: k-half select
    uint32_t aBase = smA + mt * 64;
    int aSw = (mt >> 1) & 3;
    int nt = wn * 32 + (lane & 7) + ((lane >> 4) & 1) * 8;   // B: n row
    int bkh = (lane >> 3) & 1;
    uint32_t bBase = smB + nt * 64;
    int bSw = (nt >> 1) & 3;

#pragma unroll 1
    for (int s = 0; s < 8; s++) {
        int buf = s % 3;
        if (s < 7) { CP_WAIT1(); } else { CP_WAIT0(); }
        __syncthreads();
        if (s + 2 < 8) ISSUE_STAGE(s + 2, (s + 2) % 3);    // buf (s-1)%3: free after barrier

        int bo = buf * 8192;
#pragma unroll
        for (int j = 0; j < 2; j++) {
            uint32_t aSlot = (uint32_t)(((2 * j + akh + aSw) & 3) << 4);
            uint32_t bSlot = (uint32_t)(((2 * j + bkh + bSw) & 3) << 4);
            uint32_t af[4][4];
#pragma unroll
            for (int mi = 0; mi < 4; mi++) {
                uint32_t addr = aBase + bo + mi * 1024 + aSlot;
                asm volatile("ldmatrix.sync.aligned.m8n8.x4.shared.b16 {%0,%1,%2,%3}, [%4];"
                             : "=r"(af[mi][0]), "=r"(af[mi][1]), "=r"(af[mi][2]), "=r"(af[mi][3])
                             : "r"(addr));
            }
            uint32_t bf[4][2];
#pragma unroll
            for (int p = 0; p < 2; p++) {
                uint32_t addr = bBase + bo + p * 1024 + bSlot;
                asm volatile("ldmatrix.sync.aligned.m8n8.x4.shared.b16 {%0,%1,%2,%3}, [%4];"
                             : "=r"(bf[2*p][0]), "=r"(bf[2*p][1]),
                               "=r"(bf[2*p+1][0]), "=r"(bf[2*p+1][1])
                             : "r"(addr));
            }
#pragma unroll
            for (int mi = 0; mi < 4; mi++)
#pragma unroll
                for (int ni = 0; ni < 4; ni++) {
                    asm volatile(
                        "mma.sync.aligned.m16n8k16.row.col.f32.bf16.bf16.f32 "
                        "{%0,%1,%2,%3}, {%4,%5,%6,%7}, {%8,%9}, {%0,%1,%2,%3};"
                        : "+f"(acc[mi][ni][0]), "+f"(acc[mi][ni][1]),
                          "+f"(acc[mi][ni][2]), "+f"(acc[mi][ni][3])
                        : "r"(af[mi][0]), "r"(af[mi][1]), "r"(af[mi][2]), "r"(af[mi][3]),
                          "r"(bf[ni][0]), "r"(bf[ni][1]));
                }
        }
    }

    // fused column-max over this block's 128 support rows (clamped at 0)
#pragma unroll
    for (int ni = 0; ni < 4; ni++) {
        float mA = acc[0][ni][0], mB = acc[0][ni][1];
#pragma unroll
        for (int mi = 0; mi < 4; mi++) {
            mA = fmaxf(mA, fmaxf(acc[mi][ni][0], acc[mi][ni][2]));
            mB = fmaxf(mB, fmaxf(acc[mi][ni][1], acc[mi][ni][3]));
        }
#pragma unroll
        for (int off = 16; off >= 4; off >>= 1) {
            mA = fmaxf(mA, __shfl_down_sync(0xffffffffu, mA, off));
            mB = fmaxf(mB, __shfl_down_sync(0xffffffffu, mB, off));
        }
        if (lane < 4) {
            int col = qt * 128 + wn * 32 + ni * 8 + 2 * tc;
            int* dst = g_sim + b * NHW + col;
            atomicMax(dst,     __float_as_int(fmaxf(mA, 0.f)));
            atomicMax(dst + 1, __float_as_int(fmaxf(mB, 0.f)));
        }
    }
#undef ISSUE_STAGE
}

// ---------------- K5: per-batch masked mean + log ----------------
__global__ void k_loss()
{
    __shared__ float rs[256];
    int b = blockIdx.x, tid = threadIdx.x;
    int nq = g_nq[b];
    float s = 0.f;
    for (int j = tid; j < nq; j += 256)
        s += __int_as_float(g_sim[b * NHW + j]) * g_qinvc[b * NHW + j];
    rs[tid] = s;
    __syncthreads();
    for (int off = 128; off > 0; off >>= 1) {
        if (tid < off) rs[tid] += rs[tid + off];
        __syncthreads();
    }
    if (tid == 0) {
        float pc = 0.5f * (rs[0] / fmaxf((float)nq, 1.f) + 1.f);
        g_lossb[b] = -logf(pc + 1e-8f);
    }
}

__global__ void k_out(float* __restrict__ out)
{
    if (threadIdx.x == 0)
        out[0] = 0.25f * (g_lossb[0] + g_lossb[1] + g_lossb[2] + g_lossb[3]);
}

// ---------------- launch ----------------
extern "C" void kernel_launch(void* const* d_in, const int* in_sizes, int n_in,
                              void* d_out, int out_size)
{
    const float* Qf   = (const float*)d_in[0];
    const float* Sf   = (const float*)d_in[1];
    const float* Qlab = (const float*)d_in[3];
    const float* Slab = (const float*)d_in[4];
    const float* qbg  = (const float*)d_in[5];
    const float* sbg  = (const float*)d_in[6];
    float* out = (float*)d_out;

    int write_neg = (out_size >= 1 + NB * 2 * NHW * NC) ? 1 : 0;

    k_prep<<<NB * NHW / 32, 256>>>(Qf, Sf, Qlab, Slab, qbg, sbg);
    k_compact<<<NB, 1024>>>();
    k_pack<<<dim3(NHW / 32, NC / 32, NB), dim3(32, 8)>>>(Qf, Sf, out + 1, write_neg);
    k_gemm<<<dim3(NHW / 128, NHW / 128, NB), 256>>>();
    k_loss<<<NB, 256>>>();
    k_out<<<1, 32>>>(out);
}

// round 10
// speedup vs baseline: 2.8938x; 1.0281x over previous
#include <cuda_runtime.h>
#include <cuda_bf16.h>
#include <stdint.h>

#define NB 4
#define NC 256
#define NHW 4096
#define NL 512

// ---------------- scratch (no allocations allowed) ----------------
__device__ float    g_Ql   [NB*NHW];
__device__ float    g_Qdis [NB*NHW];
__device__ float    g_Sdis [NB*NHW];
__device__ float    g_winv [NB*NHW];
__device__ float    g_qinv [NB*NHW];
__device__ float    g_qinvc[NB*NHW];
__device__ int      g_qdest[NB*NHW];
__device__ int      g_sdest[NB*NHW];
__device__ int      g_nq[NB], g_ns[NB];
__device__ int      g_sim  [NB*NHW];
__device__ uint32_t g_Ac[NB*NHW*(NC/2)];      // bf16: [b][i][k] row-major (compacted support, pre-scaled)
__device__ uint32_t g_Bc[NB*NHW*(NC/2)];      // bf16: [b][j][k] row-major (compacted query)

static __device__ __forceinline__ uint32_t packbf2(float lo, float hi) {
    __nv_bfloat162 t = __floats2bfloat162_rn(lo, hi);
    return *reinterpret_cast<uint32_t*>(&t);
}

#define CP_ASYNC16(dst, src) \
    asm volatile("cp.async.cg.shared.global [%0], [%1], 16;\n" :: "r"(dst), "l"(src))
#define CP_COMMIT() asm volatile("cp.async.commit_group;\n")
#define CP_WAIT1()  asm volatile("cp.async.wait_group 1;\n" ::: "memory")
#define CP_WAIT0()  asm volatile("cp.async.wait_group 0;\n" ::: "memory")

// ---------------- K1: labels, disrupt masks, column norms (parallel over C) ----------------
__global__ void k_prep(const float* __restrict__ Qf, const float* __restrict__ Sf,
                       const float* __restrict__ Qlab, const float* __restrict__ Slab,
                       const float* __restrict__ qbg, const float* __restrict__ sbg)
{
    __shared__ float sqs[8][33];
    __shared__ float sss[8][33];
    int blk = blockIdx.x;                  // NB*NHW/32 = 512
    int b   = blk >> 7;
    int q0  = (blk & 127) * 32;
    int tx  = threadIdx.x & 31, ty = threadIdx.x >> 5;
    int q   = q0 + tx;

    const float* Qp = Qf + ((size_t)b * NC + ty * 32) * NHW + q;
    const float* Sp = Sf + ((size_t)b * NC + ty * 32) * NHW + q;
    float sq = 0.f, ss = 0.f;
#pragma unroll
    for (int c = 0; c < 32; c++) {
        float v = Qp[(size_t)c * NHW]; sq += v * v;
        float u = Sp[(size_t)c * NHW]; ss += u * u;
    }
    sqs[ty][tx] = sq; sss[ty][tx] = ss;
    __syncthreads();

    if (ty == 0) {
        float tq = 0.f, ts = 0.f;
#pragma unroll
        for (int r = 0; r < 8; r++) { tq += sqs[r][tx]; ts += sss[r][tx]; }
        int idx = b * NHW + q;
        int h = q >> 6, w = q & 63;
        int lab = (h * 8) * NL + (w * 8);              // nearest resize 512->64
        float ql = Qlab[b * NL * NL + lab];
        float sl = Slab[b * NL * NL + lab];
        float qa = (qbg[(b * 2 + 1) * NHW + q] > qbg[(b * 2 + 0) * NHW + q]) ? 1.f : 0.f;
        float sa = (sbg[(b * 2 + 1) * NHW + q] > sbg[(b * 2 + 0) * NHW + q]) ? 1.f : 0.f;
        g_Ql[idx]   = ql;
        g_Qdis[idx] = fmaxf(1.f - qa - ql, 0.f);
        g_Sdis[idx] = fmaxf(1.f - sa - sl, 0.f);
        g_qinv[idx] = (tq > 0.f) ? 1.f / sqrtf(tq) : 0.f;
        g_winv[idx] = (sl != 0.f && ts > 0.f) ? 1.f / sqrtf(ts) : 0.f;
    }
}

// ---------------- K2: per-batch compaction via warp scans + pad/sim init ----------------
__global__ void k_compact()
{
    __shared__ int wq[32], ws[32];
    int b = blockIdx.x, tid = threadIdx.x;
    int lane = tid & 31, wid = tid >> 5;
    int base = b * NHW;

    int qf[4], sf[4];
    int lq = 0, ls = 0;
#pragma unroll
    for (int r = 0; r < 4; r++) {
        int idx = tid * 4 + r;
        qf[r] = (g_Ql[base + idx] == 1.0f);
        sf[r] = (g_winv[base + idx] > 0.f);
        lq += qf[r]; ls += sf[r];
    }
    // warp inclusive scan
    int iq = lq, is = ls;
#pragma unroll
    for (int off = 1; off < 32; off <<= 1) {
        int a = __shfl_up_sync(0xffffffffu, iq, off);
        int c = __shfl_up_sync(0xffffffffu, is, off);
        if (lane >= off) { iq += a; is += c; }
    }
    if (lane == 31) { wq[wid] = iq; ws[wid] = is; }
    __syncthreads();
    if (wid == 0) {
        int vq = wq[lane], vs = ws[lane];
#pragma unroll
        for (int off = 1; off < 32; off <<= 1) {
            int a = __shfl_up_sync(0xffffffffu, vq, off);
            int c = __shfl_up_sync(0xffffffffu, vs, off);
            if (lane >= off) { vq += a; vs += c; }
        }
        wq[lane] = vq; ws[lane] = vs;
    }
    __syncthreads();
    int qex = (wid ? wq[wid - 1] : 0) + iq - lq;
    int sex = (wid ? ws[wid - 1] : 0) + is - ls;
#pragma unroll
    for (int r = 0; r < 4; r++) {
        int idx = tid * 4 + r;
        if (qf[r]) { g_qdest[base + idx] = qex; g_qinvc[base + qex] = g_qinv[base + idx]; }
        else         g_qdest[base + idx] = -1;
        if (sf[r])   g_sdest[base + idx] = sex;
        else         g_sdest[base + idx] = -1;
        qex += qf[r]; sex += sf[r];
    }
    int nq = wq[31], ns = ws[31];
    if (tid == 0) { g_nq[b] = nq; g_ns[b] = ns; }

    for (int i = tid; i < NHW; i += 1024) g_sim[base + i] = 0;

    int nsp = (ns + 127) & ~127;
    for (int i = tid; i < (nsp - ns) * 128; i += 1024) {
        int row = ns + (i >> 7), kp = i & 127;
        g_Ac[((size_t)base + row) * 128 + kp] = 0;
    }
    int nqp = (nq + 127) & ~127;
    for (int i = tid; i < (nqp - nq) * 128; i += 1024) {
        int row = nq + (i >> 7), kp = i & 127;
        g_Bc[((size_t)base + row) * 128 + kp] = 0;
    }
}

// ---------------- K3: negatives + compacted bf16 operand packing ----------------
__global__ void k_pack(const float* __restrict__ Qf, const float* __restrict__ Sf,
                       float* __restrict__ neg, int write_neg)
{
    __shared__ float Qt[32][33];
    __shared__ float St[32][33];
    int b  = blockIdx.z;
    int q0 = blockIdx.x * 32;
    int c0 = blockIdx.y * 32;
    int tx = threadIdx.x, ty = threadIdx.y;

    const float* Qbase = Qf + ((size_t)b * NC + c0) * NHW + q0;
    const float* Sbase = Sf + ((size_t)b * NC + c0) * NHW + q0;
#pragma unroll
    for (int r = 0; r < 4; r++) {
        int c = ty + r * 8;
        Qt[c][tx] = Qbase[(size_t)c * NHW + tx];
        St[c][tx] = Sbase[(size_t)c * NHW + tx];
    }
    __syncthreads();

    if (write_neg) {
#pragma unroll
        for (int r = 0; r < 4; r++) {
            int ql = ty + r * 8;
            int q  = q0 + ql;
            float qd = g_Qdis[b * NHW + q];
            float sd = g_Sdis[b * NHW + q];
            neg[(((size_t)b * 2 + 0) * NHW + q) * NC + c0 + tx] = Qt[tx][ql] * qd;
            neg[(((size_t)b * 2 + 1) * NHW + q) * NC + c0 + tx] = St[tx][ql] * sd;
        }
    }
    int tid = ty * 32 + tx;
    // B operand: [b][j][kp] (compacted queries)
#pragma unroll
    for (int r = 0; r < 2; r++) {
        int ent = tid + r * 256;
        int sl  = ent >> 4;
        int kpl = ent & 15;
        int j = g_qdest[b * NHW + q0 + sl];
        if (j >= 0) {
            g_Bc[((size_t)b * NHW + j) * 128 + c0 / 2 + kpl] =
                packbf2(Qt[2 * kpl][sl], Qt[2 * kpl + 1][sl]);
        }
    }
    // A operand: [b][i][kp] (compacted support, pre-scaled by Sl/|S_col|)
#pragma unroll
    for (int r = 0; r < 2; r++) {
        int ent = tid + r * 256;
        int sl  = ent >> 4;
        int kpl = ent & 15;
        int i = g_sdest[b * NHW + q0 + sl];
        if (i >= 0) {
            float wv = g_winv[b * NHW + q0 + sl];
            g_Ac[((size_t)b * NHW + i) * 128 + c0 / 2 + kpl] =
                packbf2(St[2 * kpl][sl] * wv, St[2 * kpl + 1][sl] * wv);
        }
    }
}

// ---------------- K4: ldmatrix + cp.async bf16 mma GEMM, 64-k stages ----------------
// Tile 128x128, K=256 in 4 stages of 64 k (8 uint4 chunks/row/stage).
// 3 buffers x 32KB = 96KB dynamic smem, 1 barrier per stage.
// smem row = 128B, swizzle: phys_chunk = chunk ^ (row & 7)  (conflict-free LDSM octets)
__global__ void __launch_bounds__(256, 2) k_gemm()
{
    extern __shared__ __align__(128) uint4 dsm[];

    int b  = blockIdx.z;
    int qt = blockIdx.x;
    int st = blockIdx.y;
    if (st * 128 >= g_ns[b] || qt * 128 >= g_nq[b]) return;

    int tid  = threadIdx.x;
    int warp = tid >> 5, lane = tid & 31;
    int wm = warp >> 2, wn = warp & 3;      // 2x4 warps -> 64x32 warp tiles
    int tc = lane & 3;

    float acc[4][4][4];
#pragma unroll
    for (int mi = 0; mi < 4; mi++)
#pragma unroll
        for (int ni = 0; ni < 4; ni++)
#pragma unroll
            for (int r = 0; r < 4; r++) acc[mi][ni][r] = 0.f;

    const uint4* gA = (const uint4*)(g_Ac + ((size_t)b * NHW + (size_t)st * 128) * 128);
    const uint4* gB = (const uint4*)(g_Bc + ((size_t)b * NHW + (size_t)qt * 128) * 128);

    uint32_t smem_base = (uint32_t)__cvta_generic_to_shared(dsm);
    const uint32_t B_OFF = 3 * 16384;       // B region after 3 A buffers

    // loader mapping: 2 threads/row, each 4 consecutive chunks (64B) per operand
    int lrow  = tid >> 1;
    int lhalf = (tid & 1) * 4;
    int lsw   = lrow & 7;
    const uint4* gArow = gA + (size_t)lrow * 32;
    const uint4* gBrow = gB + (size_t)lrow * 32;
    uint32_t sA = smem_base + lrow * 128;
    uint32_t sB = smem_base + B_OFF + lrow * 128;

#define ISSUE_STAGE(s, buf) do {                                            \
        uint32_t _o = (uint32_t)(buf) * 16384u;                             \
        _Pragma("unroll")                                                   \
        for (int i = 0; i < 4; i++)                                         \
            CP_ASYNC16(sA + _o + (uint32_t)(((lhalf + i) ^ lsw) << 4),      \
                       gArow + (s) * 8 + lhalf + i);                        \
        _Pragma("unroll")                                                   \
        for (int i = 0; i < 4; i++)                                         \
            CP_ASYNC16(sB + _o + (uint32_t)(((lhalf + i) ^ lsw) << 4),      \
                       gBrow + (s) * 8 + lhalf + i);                        \
        CP_COMMIT();                                                        \
    } while (0)

    ISSUE_STAGE(0, 0);
    ISSUE_STAGE(1, 1);

    // LDSM thread->address precompute
    int mt15 = lane & 15;                         // A row within 16 (mi adds 16)
    int akh  = lane >> 4;                         // A k-half (chunk parity)
    int asw  = mt15 & 7;
    uint32_t aBase = smem_base + (wm * 64 + mt15) * 128;
    int ntl  = wn * 32 + (lane & 7) + ((lane >> 4) & 1) * 8;  // B row (p adds 16)
    int bkh  = (lane >> 3) & 1;
    int bsw  = lane & 7;                          // ntl & 7 == lane & 7
    uint32_t bBase = smem_base + B_OFF + ntl * 128;

#pragma unroll 1
    for (int s = 0; s < 4; s++) {
        int buf = s % 3;
        if (s < 3) { CP_WAIT1(); } else { CP_WAIT0(); }
        __syncthreads();
        if (s < 2) ISSUE_STAGE(s + 2, (s + 2) % 3);   // buf (s-1)%3: free after barrier

        uint32_t bo = (uint32_t)buf * 16384u;
#pragma unroll
        for (int j = 0; j < 4; j++) {
            uint32_t aSlot = (uint32_t)((((2 * j + akh) ^ asw) & 7) << 4);
            uint32_t bSlot = (uint32_t)((((2 * j + bkh) ^ bsw) & 7) << 4);
            uint32_t af[4][4];
#pragma unroll
            for (int mi = 0; mi < 4; mi++) {
                uint32_t addr = aBase + bo + mi * 2048 + aSlot;
                asm volatile("ldmatrix.sync.aligned.m8n8.x4.shared.b16 {%0,%1,%2,%3}, [%4];"
                             : "=r"(af[mi][0]), "=r"(af[mi][1]), "=r"(af[mi][2]), "=r"(af[mi][3])
                             : "r"(addr));
            }
            uint32_t bf[4][2];
#pragma unroll
            for (int p = 0; p < 2; p++) {
                uint32_t addr = bBase + bo + p * 2048 + bSlot;
                asm volatile("ldmatrix.sync.aligned.m8n8.x4.shared.b16 {%0,%1,%2,%3}, [%4];"
                             : "=r"(bf[2*p][0]), "=r"(bf[2*p][1]),
                               "=r"(bf[2*p+1][0]), "=r"(bf[2*p+1][1])
                             : "r"(addr));
            }
#pragma unroll
            for (int mi = 0; mi < 4; mi++)
#pragma unroll
                for (int ni = 0; ni < 4; ni++) {
                    asm volatile(
                        "mma.sync.aligned.m16n8k16.row.col.f32.bf16.bf16.f32 "
                        "{%0,%1,%2,%3}, {%4,%5,%6,%7}, {%8,%9}, {%0,%1,%2,%3};"
                        : "+f"(acc[mi][ni][0]), "+f"(acc[mi][ni][1]),
                          "+f"(acc[mi][ni][2]), "+f"(acc[mi][ni][3])
                        : "r"(af[mi][0]), "r"(af[mi][1]), "r"(af[mi][2]), "r"(af[mi][3]),
                          "r"(bf[ni][0]), "r"(bf[ni][1]));
                }
        }
    }

    // fused column-max over this block's 128 support rows (clamped at 0)
#pragma unroll
    for (int ni = 0; ni < 4; ni++) {
        float mA = acc[0][ni][0], mB = acc[0][ni][1];
#pragma unroll
        for (int mi = 0; mi < 4; mi++) {
            mA = fmaxf(mA, fmaxf(acc[mi][ni][0], acc[mi][ni][2]));
            mB = fmaxf(mB, fmaxf(acc[mi][ni][1], acc[mi][ni][3]));
        }
#pragma unroll
        for (int off = 16; off >= 4; off >>= 1) {
            mA = fmaxf(mA, __shfl_down_sync(0xffffffffu, mA, off));
            mB = fmaxf(mB, __shfl_down_sync(0xffffffffu, mB, off));
        }
        if (lane < 4) {
            int col = qt * 128 + wn * 32 + ni * 8 + 2 * tc;
            int* dst = g_sim + b * NHW + col;
            atomicMax(dst,     __float_as_int(fmaxf(mA, 0.f)));
            atomicMax(dst + 1, __float_as_int(fmaxf(mB, 0.f)));
        }
    }
#undef ISSUE_STAGE
}

// ---------------- K5: fused per-batch masked mean + log + output ----------------
__global__ void k_lossout(float* __restrict__ out)
{
    __shared__ float rs[1024];
    __shared__ float lb[4];
    int tid = threadIdx.x;
    int b = tid >> 8, t = tid & 255;
    int nq = g_nq[b];
    float s = 0.f;
    for (int j = t; j < nq; j += 256)
        s += __int_as_float(g_sim[b * NHW + j]) * g_qinvc[b * NHW + j];
    rs[tid] = s;
    __syncthreads();
    for (int off = 128; off > 0; off >>= 1) {
        if (t < off) rs[tid] += rs[tid + off];
        __syncthreads();
    }
    if (t == 0) {
        float pc = 0.5f * (rs[tid] / fmaxf((float)nq, 1.f) + 1.f);
        lb[b] = -logf(pc + 1e-8f);
    }
    __syncthreads();
    if (tid == 0)
        out[0] = 0.25f * (lb[0] + lb[1] + lb[2] + lb[3]);
}

// ---------------- launch ----------------
extern "C" void kernel_launch(void* const* d_in, const int* in_sizes, int n_in,
                              void* d_out, int out_size)
{
    const float* Qf   = (const float*)d_in[0];
    const float* Sf   = (const float*)d_in[1];
    const float* Qlab = (const float*)d_in[3];
    const float* Slab = (const float*)d_in[4];
    const float* qbg  = (const float*)d_in[5];
    const float* sbg  = (const float*)d_in[6];
    float* out = (float*)d_out;

    int write_neg = (out_size >= 1 + NB * 2 * NHW * NC) ? 1 : 0;

    // idempotent, host-side, capture-safe; called every launch (no static guards)
    cudaFuncSetAttribute(k_gemm, cudaFuncAttributeMaxDynamicSharedMemorySize, 98304);

    k_prep<<<NB * NHW / 32, 256>>>(Qf, Sf, Qlab, Slab, qbg, sbg);
    k_compact<<<NB, 1024>>>();
    k_pack<<<dim3(NHW / 32, NC / 32, NB), dim3(32, 8)>>>(Qf, Sf, out + 1, write_neg);
    k_gemm<<<dim3(NHW / 128, NHW / 128, NB), 256, 98304>>>();
    k_lossout<<<1, 1024>>>(out);
}